// round 13
// baseline (speedup 1.0000x reference)
#include <cuda_runtime.h>

#define NANTS 8
#define NT 16
#define NF 32
#define NS 1024
#define NBL 28
#define NE (NBL * NT * NF)    // 14336
#define NCELL (NT * NF)       // 512
#define NTHREADS 128
#define NWARPS (NTHREADS / 32)

#define PI2_HI 6.2831854820251464844f   // 2*pi rounded to fp32
#define INV_2PI 0.15915494309189533577f
#define NEG_2PI_OVER_C (-2.0958450219516946e-8f)  // -2*pi / 299792458 (exact C)

// Cross-block combine state (graph-replay safe: atomicInc(...,1) wraps 1->0,
// so counters self-reset to 0 after every call).
__device__ float        g_part[2 * NE];
__device__ unsigned int g_cnt[NCELL];

// Gram factorization, Re only:
//   Re(vis_ij)(t,f) = sum_s u_i*u_j + v_i*v_j,
//   (u_a, v_a) = g_a*(cos ph_a, sin ph_a), ph_a = -2*pi*f*(r_a.s_hat)/C,
//   g_a = sqrt(sky)*beam[m_a]
// Grid 1024 = (t,f) x source-half. Last block per cell combines the halves.
__global__ __launch_bounds__(NTHREADS, 8) void rime_gram_re_kernel(
    const float* __restrict__ sky,      // [NF, NS]
    const float* __restrict__ beam,     // [2, NT, NF, NS]
    const float* __restrict__ antpos,   // [NANTS, 3]
    const float* __restrict__ src,      // [NT, NS, 3]
    const float* __restrict__ freqs,    // [NF]
    const int*   __restrict__ a2m,      // [NANTS]
    const int*   __restrict__ bls,      // [NBL, 2]
    float*       __restrict__ out)      // [NBL, NT, NF] float32 = Re(vis)
{
    const int cell = blockIdx.x >> 1;
    const int half = blockIdx.x & 1;
    const int t   = cell >> 5;
    const int f   = cell & (NF - 1);
    const int tid = threadIdx.x;

    const float kc = __ldg(&freqs[f]) * NEG_2PI_OVER_C;

    float kax[NANTS], kay[NANTS], kaz[NANTS];
    int   m[NANTS];
#pragma unroll
    for (int a = 0; a < NANTS; a++) {
        kax[a] = kc * __ldg(&antpos[a * 3 + 0]);
        kay[a] = kc * __ldg(&antpos[a * 3 + 1]);
        kaz[a] = kc * __ldg(&antpos[a * 3 + 2]);
        m[a]  = __ldg(&a2m[a]);
    }

    float accr[NBL];
#pragma unroll
    for (int p = 0; p < NBL; p++) accr[p] = 0.0f;

    const float* __restrict__ beam0 = beam + ((size_t)(0 * NT + t) * NF + f) * NS;
    const float* __restrict__ beam1 = beam + ((size_t)(1 * NT + t) * NF + f) * NS;
    const float* __restrict__ skyf  = sky + (size_t)f * NS;
    const float* __restrict__ srct  = src + (size_t)t * NS * 3;

    const int s0 = half * (NS / 2) + tid;
#pragma unroll 2
    for (int k = 0; k < 4; k++) {
        const int s = s0 + k * NTHREADS;
        const float dx = __ldg(&srct[s * 3 + 0]);
        const float dy = __ldg(&srct[s * 3 + 1]);
        const float dz = __ldg(&srct[s * 3 + 2]);
        const float sk = sqrtf(__ldg(&skyf[s]));
        const float g0 = __ldg(&beam0[s]) * sk;
        const float g1 = __ldg(&beam1[s]) * sk;

        float u[NANTS], v[NANTS];
#pragma unroll
        for (int a = 0; a < NANTS; a++) {
            float ph = fmaf(kax[a], dx, fmaf(kay[a], dy, kaz[a] * dz));
            // single-word range reduction (residual n*1.75e-7 <= 2e-5 rad)
            const float n = rintf(ph * INV_2PI);
            ph = fmaf(-n, PI2_HI, ph);
            float sn, cs;
            __sincosf(ph, &sn, &cs);
            const float g = m[a] ? g1 : g0;
            u[a] = g * cs;
            v[a] = g * sn;
        }

        int p = 0;
#pragma unroll
        for (int i = 0; i < NANTS; i++) {
#pragma unroll
            for (int j = i + 1; j < NANTS; j++) {
                accr[p] = fmaf(u[i], u[j], fmaf(v[i], v[j], accr[p]));
                p++;
            }
        }
    }

    // intra-warp butterfly reduction of 28 floats
#pragma unroll
    for (int p = 0; p < NBL; p++) {
#pragma unroll
        for (int off = 16; off > 0; off >>= 1) {
            accr[p] += __shfl_xor_sync(0xffffffffu, accr[p], off);
        }
    }

    __shared__ float red[NWARPS][NBL];
    const int w = tid >> 5, lane = tid & 31;
    if (lane == 0) {
#pragma unroll
        for (int p = 0; p < NBL; p++) red[w][p] = accr[p];
    }
    __syncthreads();

    if (tid < NBL) {
        // bls verified canonical (i<j ascending); remap kept for robustness.
        int bi = __ldg(&bls[2 * tid]);
        int bj = __ldg(&bls[2 * tid + 1]);
        if (bi > bj) { int tmp = bi; bi = bj; bj = tmp; }
        const int pc = bi * (2 * NANTS - bi - 1) / 2 + (bj - bi - 1);
        float r = 0.0f;
#pragma unroll
        for (int ww = 0; ww < NWARPS; ww++) r += red[ww][pc];
        g_part[half * NE + (tid * NT + t) * NF + f] = r;
    }

    // Last block for this cell combines the two halves.
    __threadfence();
    __shared__ unsigned int ticket;
    if (tid == 0) ticket = atomicInc(&g_cnt[cell], 1);  // wraps 1 -> 0
    __syncthreads();
    if (ticket == 1) {
        __threadfence();
        if (tid < NBL) {
            const int idx = (tid * NT + t) * NF + f;
            out[idx] = g_part[idx] + g_part[NE + idx];
        }
    }
}

extern "C" void kernel_launch(void* const* d_in, const int* in_sizes, int n_in,
                              void* d_out, int out_size) {
    (void)out_size;
    const float* sky = nullptr;     // 32768
    const float* beam = nullptr;    // 1048576
    const float* antpos = nullptr;  // 24
    const float* src = nullptr;     // 49152
    const float* freqs = nullptr;   // 32
    const int*   a2m = nullptr;     // 8
    const int*   bls = nullptr;     // 56
    for (int k = 0; k < n_in; k++) {
        switch (in_sizes[k]) {
            case 32768:   sky    = (const float*)d_in[k]; break;
            case 1048576: beam   = (const float*)d_in[k]; break;
            case 24:      antpos = (const float*)d_in[k]; break;
            case 49152:   src    = (const float*)d_in[k]; break;
            case 32:      freqs  = (const float*)d_in[k]; break;
            case 8:       a2m    = (const int*)d_in[k];   break;
            case 56:      bls    = (const int*)d_in[k];   break;
            default: break;
        }
    }

    rime_gram_re_kernel<<<2 * NCELL, NTHREADS>>>(
        sky, beam, antpos, src, freqs, a2m, bls, (float*)d_out);
}

// round 14
// speedup vs baseline: 1.2182x; 1.2182x over previous
#include <cuda_runtime.h>

#define NANTS 8
#define NT 16
#define NF 32
#define NS 1024
#define NBL 28
#define NTHREADS 128
#define NWARPS (NTHREADS / 32)

#define PI2_HI 6.2831854820251464844f   // 2*pi rounded to fp32
#define INV_2PI 0.15915494309189533577f
#define NEG_2PI_OVER_C (-2.0958450219516946e-8f)  // -2*pi / 299792458 (exact C)

typedef unsigned long long u64;

__device__ __forceinline__ u64 pack2(float lo, float hi) {
    u64 r;
    asm("mov.b64 %0, {%1, %2};" : "=l"(r) : "f"(lo), "f"(hi));
    return r;
}
__device__ __forceinline__ void unpack2(u64 v, float& lo, float& hi) {
    asm("mov.b64 {%0, %1}, %2;" : "=f"(lo), "=f"(hi) : "l"(v));
}
__device__ __forceinline__ u64 fma2(u64 a, u64 b, u64 c) {
    u64 d;
    asm("fma.rn.f32x2 %0, %1, %2, %3;" : "=l"(d) : "l"(a), "l"(b), "l"(c));
    return d;
}
__device__ __forceinline__ u64 mul2(u64 a, u64 b) {
    u64 d;
    asm("mul.rn.f32x2 %0, %1, %2;" : "=l"(d) : "l"(a), "l"(b));
    return d;
}
__device__ __forceinline__ float sqrt_approx(float x) {
    float r;
    asm("sqrt.approx.f32 %0, %1;" : "=f"(r) : "f"(x));
    return r;
}

// Gram factorization, Re only, f32x2-packed inner math:
//   Re(vis_ij)(t,f) = sum_s u_i*u_j + v_i*v_j
//   (u_a, v_a) = g_a*(cos ph_a, sin ph_a), ph_a = -2*pi*f*(r_a.s_hat)/C
//   g_a = sqrt(sky)*beam[m_a]
// One block per (t,f), 128 threads, 8 sources/thread (best-known shape, R10).
__global__ __launch_bounds__(NTHREADS, 4) void rime_gram_re_kernel(
    const float* __restrict__ sky,      // [NF, NS]
    const float* __restrict__ beam,     // [2, NT, NF, NS]
    const float* __restrict__ antpos,   // [NANTS, 3]
    const float* __restrict__ src,      // [NT, NS, 3]
    const float* __restrict__ freqs,    // [NF]
    const int*   __restrict__ a2m,      // [NANTS]
    const int*   __restrict__ bls,      // [NBL, 2]
    float*       __restrict__ out)      // [NBL, NT, NF] float32 = Re(vis)
{
    const int tf  = blockIdx.x;
    const int t   = tf >> 5;
    const int f   = tf & (NF - 1);
    const int tid = threadIdx.x;

    const float kc = __ldg(&freqs[f]) * NEG_2PI_OVER_C;

    // Packed per-antenna-pair phase coefficients: lane = antennas (2q, 2q+1)
    u64 KX[NANTS / 2], KY[NANTS / 2], KZ[NANTS / 2];
    int m[NANTS];
#pragma unroll
    for (int q = 0; q < NANTS / 2; q++) {
        const int a = 2 * q, b = 2 * q + 1;
        KX[q] = pack2(kc * __ldg(&antpos[a * 3 + 0]), kc * __ldg(&antpos[b * 3 + 0]));
        KY[q] = pack2(kc * __ldg(&antpos[a * 3 + 1]), kc * __ldg(&antpos[b * 3 + 1]));
        KZ[q] = pack2(kc * __ldg(&antpos[a * 3 + 2]), kc * __ldg(&antpos[b * 3 + 2]));
    }
#pragma unroll
    for (int a = 0; a < NANTS; a++) m[a] = __ldg(&a2m[a]);

    // Packed accumulators: acc2[p] = (sum u_i*u_j, sum v_i*v_j)
    u64 acc2[NBL];
#pragma unroll
    for (int p = 0; p < NBL; p++) acc2[p] = 0ull;

    const float* __restrict__ beam0 = beam + ((size_t)(0 * NT + t) * NF + f) * NS;
    const float* __restrict__ beam1 = beam + ((size_t)(1 * NT + t) * NF + f) * NS;
    const float* __restrict__ skyf  = sky + (size_t)f * NS;
    const float* __restrict__ srct  = src + (size_t)t * NS * 3;

#pragma unroll 2
    for (int s = tid; s < NS; s += NTHREADS) {
        const float dx = __ldg(&srct[s * 3 + 0]);
        const float dy = __ldg(&srct[s * 3 + 1]);
        const float dz = __ldg(&srct[s * 3 + 2]);
        const float sk = sqrt_approx(__ldg(&skyf[s]));
        const float g0 = __ldg(&beam0[s]) * sk;
        const float g1 = __ldg(&beam1[s]) * sk;

        const u64 DX = pack2(dx, dx), DY = pack2(dy, dy), DZ = pack2(dz, dz);

        u64 U[NANTS];   // U[a] = (g_a*cos, g_a*sin)
#pragma unroll
        for (int q = 0; q < NANTS / 2; q++) {
            const u64 ph2 = fma2(KX[q], DX, fma2(KY[q], DY, mul2(KZ[q], DZ)));
            float pha, phb;
            unpack2(ph2, pha, phb);
#pragma unroll
            for (int h = 0; h < 2; h++) {
                float ph = h ? phb : pha;
                const int a = 2 * q + h;
                // single-word range reduction (residual <= 2e-5 rad)
                const float n = rintf(ph * INV_2PI);
                ph = fmaf(-n, PI2_HI, ph);
                float sn, cs;
                __sincosf(ph, &sn, &cs);
                const float g = m[a] ? g1 : g0;
                U[a] = mul2(pack2(cs, sn), pack2(g, g));
            }
        }

        int p = 0;
#pragma unroll
        for (int i = 0; i < NANTS; i++) {
#pragma unroll
            for (int j = i + 1; j < NANTS; j++) {
                acc2[p] = fma2(U[i], U[j], acc2[p]);   // (uu, vv) accumulate
                p++;
            }
        }
    }

    // Unpack to Re = uu + vv, then intra-warp butterfly reduction.
    float accr[NBL];
#pragma unroll
    for (int p = 0; p < NBL; p++) {
        float lo, hi;
        unpack2(acc2[p], lo, hi);
        accr[p] = lo + hi;
    }
#pragma unroll
    for (int p = 0; p < NBL; p++) {
#pragma unroll
        for (int off = 16; off > 0; off >>= 1) {
            accr[p] += __shfl_xor_sync(0xffffffffu, accr[p], off);
        }
    }

    __shared__ float red[NWARPS][NBL];
    const int w = tid >> 5, lane = tid & 31;
    if (lane == 0) {
#pragma unroll
        for (int p = 0; p < NBL; p++) red[w][p] = accr[p];
    }
    __syncthreads();

    if (tid < NBL) {
        // bls verified canonical (i<j ascending); remap kept for robustness.
        int bi = __ldg(&bls[2 * tid]);
        int bj = __ldg(&bls[2 * tid + 1]);
        if (bi > bj) { int tmp = bi; bi = bj; bj = tmp; }
        const int pc = bi * (2 * NANTS - bi - 1) / 2 + (bj - bi - 1);
        float r = 0.0f;
#pragma unroll
        for (int ww = 0; ww < NWARPS; ww++) r += red[ww][pc];
        out[(tid * NT + t) * NF + f] = r;   // (b, t, f) C-order, Re(vis)
    }
}

extern "C" void kernel_launch(void* const* d_in, const int* in_sizes, int n_in,
                              void* d_out, int out_size) {
    (void)out_size;
    const float* sky = nullptr;     // 32768
    const float* beam = nullptr;    // 1048576
    const float* antpos = nullptr;  // 24
    const float* src = nullptr;     // 49152
    const float* freqs = nullptr;   // 32
    const int*   a2m = nullptr;     // 8
    const int*   bls = nullptr;     // 56
    for (int k = 0; k < n_in; k++) {
        switch (in_sizes[k]) {
            case 32768:   sky    = (const float*)d_in[k]; break;
            case 1048576: beam   = (const float*)d_in[k]; break;
            case 24:      antpos = (const float*)d_in[k]; break;
            case 49152:   src    = (const float*)d_in[k]; break;
            case 32:      freqs  = (const float*)d_in[k]; break;
            case 8:       a2m    = (const int*)d_in[k];   break;
            case 56:      bls    = (const int*)d_in[k];   break;
            default: break;
        }
    }

    rime_gram_re_kernel<<<NT * NF, NTHREADS>>>(
        sky, beam, antpos, src, freqs, a2m, bls, (float*)d_out);
}

// round 15
// speedup vs baseline: 1.3673x; 1.1224x over previous
#include <cuda_runtime.h>

#define NANTS 8
#define NT 16
#define NF 32
#define NS 1024
#define NBL 28
#define NTHREADS 128
#define NWARPS (NTHREADS / 32)

#define NEG_2PI_OVER_C (-2.0958450219516946e-8f)  // -2*pi / 299792458 (exact C)

typedef unsigned long long u64;

__device__ __forceinline__ u64 pack2(float lo, float hi) {
    u64 r;
    asm("mov.b64 %0, {%1, %2};" : "=l"(r) : "f"(lo), "f"(hi));
    return r;
}
__device__ __forceinline__ void unpack2(u64 v, float& lo, float& hi) {
    asm("mov.b64 {%0, %1}, %2;" : "=f"(lo), "=f"(hi) : "l"(v));
}
__device__ __forceinline__ u64 fma2(u64 a, u64 b, u64 c) {
    u64 d;
    asm("fma.rn.f32x2 %0, %1, %2, %3;" : "=l"(d) : "l"(a), "l"(b), "l"(c));
    return d;
}
__device__ __forceinline__ u64 mul2(u64 a, u64 b) {
    u64 d;
    asm("mul.rn.f32x2 %0, %1, %2;" : "=l"(d) : "l"(a), "l"(b));
    return d;
}
__device__ __forceinline__ float sqrt_approx(float x) {
    float r;
    asm("sqrt.approx.f32 %0, %1;" : "=f"(r) : "f"(x));
    return r;
}
__device__ __forceinline__ float sin_ap(float x) {
    float r;
    asm("sin.approx.f32 %0, %1;" : "=f"(r) : "f"(x));
    return r;
}
__device__ __forceinline__ float cos_ap(float x) {
    float r;
    asm("cos.approx.f32 %0, %1;" : "=f"(r) : "f"(x));
    return r;
}

// Gram factorization, Re only, f32x2-packed, HW-only range reduction:
//   Re(vis_ij)(t,f) = sum_s u_i*u_j + v_i*v_j
//   (u_a, v_a) = g_a*(cos ph_a, sin ph_a), ph_a = -2*pi*f*(r_a.s_hat)/C
//   |ph| <= ~320 rad; MUFU's internal reduction error ~ph*2^-23 <= 4e-5 rad.
// One block per (t,f), 128 threads, 8 sources/thread.
__global__ __launch_bounds__(NTHREADS, 4) void rime_gram_re_kernel(
    const float* __restrict__ sky,      // [NF, NS]
    const float* __restrict__ beam,     // [2, NT, NF, NS]
    const float* __restrict__ antpos,   // [NANTS, 3]
    const float* __restrict__ src,      // [NT, NS, 3]
    const float* __restrict__ freqs,    // [NF]
    const int*   __restrict__ a2m,      // [NANTS]
    const int*   __restrict__ bls,      // [NBL, 2]
    float*       __restrict__ out)      // [NBL, NT, NF] float32 = Re(vis)
{
    const int tf  = blockIdx.x;
    const int t   = tf >> 5;
    const int f   = tf & (NF - 1);
    const int tid = threadIdx.x;

    const float kc = __ldg(&freqs[f]) * NEG_2PI_OVER_C;

    // Packed per-antenna-pair phase coefficients: lanes = antennas (2q, 2q+1)
    u64 KX[NANTS / 2], KY[NANTS / 2], KZ[NANTS / 2];
    int m[NANTS];
#pragma unroll
    for (int q = 0; q < NANTS / 2; q++) {
        const int a = 2 * q, b = 2 * q + 1;
        KX[q] = pack2(kc * __ldg(&antpos[a * 3 + 0]), kc * __ldg(&antpos[b * 3 + 0]));
        KY[q] = pack2(kc * __ldg(&antpos[a * 3 + 1]), kc * __ldg(&antpos[b * 3 + 1]));
        KZ[q] = pack2(kc * __ldg(&antpos[a * 3 + 2]), kc * __ldg(&antpos[b * 3 + 2]));
    }
#pragma unroll
    for (int a = 0; a < NANTS; a++) m[a] = __ldg(&a2m[a]);

    // Packed accumulators: acc2[p] = (sum u_i*u_j, sum v_i*v_j)
    u64 acc2[NBL];
#pragma unroll
    for (int p = 0; p < NBL; p++) acc2[p] = 0ull;

    const float* __restrict__ beam0 = beam + ((size_t)(0 * NT + t) * NF + f) * NS;
    const float* __restrict__ beam1 = beam + ((size_t)(1 * NT + t) * NF + f) * NS;
    const float* __restrict__ skyf  = sky + (size_t)f * NS;
    const float* __restrict__ srct  = src + (size_t)t * NS * 3;

#pragma unroll 2
    for (int s = tid; s < NS; s += NTHREADS) {
        const float dx = __ldg(&srct[s * 3 + 0]);
        const float dy = __ldg(&srct[s * 3 + 1]);
        const float dz = __ldg(&srct[s * 3 + 2]);
        const float sk = sqrt_approx(__ldg(&skyf[s]));
        const float g0 = __ldg(&beam0[s]) * sk;
        const float g1 = __ldg(&beam1[s]) * sk;
        const u64 G0 = pack2(g0, g0), G1 = pack2(g1, g1);

        const u64 DX = pack2(dx, dx), DY = pack2(dy, dy), DZ = pack2(dz, dz);

        u64 U[NANTS];   // U[a] = (g_a*cos, g_a*sin)
#pragma unroll
        for (int q = 0; q < NANTS / 2; q++) {
            const u64 ph2 = fma2(KX[q], DX, fma2(KY[q], DY, mul2(KZ[q], DZ)));
            float pha, phb;
            unpack2(ph2, pha, phb);
#pragma unroll
            for (int h = 0; h < 2; h++) {
                const float ph = h ? phb : pha;
                const int a = 2 * q + h;
                // HW range reduction only (MUFU): |ph|<=320 rad -> ~4e-5 rad err
                const float cs = cos_ap(ph);
                const float sn = sin_ap(ph);
                U[a] = mul2(pack2(cs, sn), m[a] ? G1 : G0);
            }
        }

        int p = 0;
#pragma unroll
        for (int i = 0; i < NANTS; i++) {
#pragma unroll
            for (int j = i + 1; j < NANTS; j++) {
                acc2[p] = fma2(U[i], U[j], acc2[p]);   // (uu, vv) accumulate
                p++;
            }
        }
    }

    // Unpack to Re = uu + vv, then intra-warp butterfly reduction.
    float accr[NBL];
#pragma unroll
    for (int p = 0; p < NBL; p++) {
        float lo, hi;
        unpack2(acc2[p], lo, hi);
        accr[p] = lo + hi;
    }
#pragma unroll
    for (int p = 0; p < NBL; p++) {
#pragma unroll
        for (int off = 16; off > 0; off >>= 1) {
            accr[p] += __shfl_xor_sync(0xffffffffu, accr[p], off);
        }
    }

    __shared__ float red[NWARPS][NBL];
    const int w = tid >> 5, lane = tid & 31;
    if (lane == 0) {
#pragma unroll
        for (int p = 0; p < NBL; p++) red[w][p] = accr[p];
    }
    __syncthreads();

    if (tid < NBL) {
        // bls verified canonical (i<j ascending); remap kept for robustness.
        int bi = __ldg(&bls[2 * tid]);
        int bj = __ldg(&bls[2 * tid + 1]);
        if (bi > bj) { int tmp = bi; bi = bj; bj = tmp; }
        const int pc = bi * (2 * NANTS - bi - 1) / 2 + (bj - bi - 1);
        float r = 0.0f;
#pragma unroll
        for (int ww = 0; ww < NWARPS; ww++) r += red[ww][pc];
        out[(tid * NT + t) * NF + f] = r;   // (b, t, f) C-order, Re(vis)
    }
}

extern "C" void kernel_launch(void* const* d_in, const int* in_sizes, int n_in,
                              void* d_out, int out_size) {
    (void)out_size;
    const float* sky = nullptr;     // 32768
    const float* beam = nullptr;    // 1048576
    const float* antpos = nullptr;  // 24
    const float* src = nullptr;     // 49152
    const float* freqs = nullptr;   // 32
    const int*   a2m = nullptr;     // 8
    const int*   bls = nullptr;     // 56
    for (int k = 0; k < n_in; k++) {
        switch (in_sizes[k]) {
            case 32768:   sky    = (const float*)d_in[k]; break;
            case 1048576: beam   = (const float*)d_in[k]; break;
            case 24:      antpos = (const float*)d_in[k]; break;
            case 49152:   src    = (const float*)d_in[k]; break;
            case 32:      freqs  = (const float*)d_in[k]; break;
            case 8:       a2m    = (const int*)d_in[k];   break;
            case 56:      bls    = (const int*)d_in[k];   break;
            default: break;
        }
    }

    rime_gram_re_kernel<<<NT * NF, NTHREADS>>>(
        sky, beam, antpos, src, freqs, a2m, bls, (float*)d_out);
}

// round 16
// speedup vs baseline: 1.4431x; 1.0554x over previous
#include <cuda_runtime.h>

#define NANTS 8
#define NT 16
#define NF 32
#define NS 1024
#define NBL 28
#define NTHREADS 128
#define NWARPS (NTHREADS / 32)
#define NITER (NS / NTHREADS)   // 8 sources per thread

#define NEG_2PI_OVER_C (-2.0958450219516946e-8f)  // -2*pi / 299792458 (exact C)

typedef unsigned long long u64;

__device__ __forceinline__ u64 pack2(float lo, float hi) {
    u64 r;
    asm("mov.b64 %0, {%1, %2};" : "=l"(r) : "f"(lo), "f"(hi));
    return r;
}
__device__ __forceinline__ void unpack2(u64 v, float& lo, float& hi) {
    asm("mov.b64 {%0, %1}, %2;" : "=f"(lo), "=f"(hi) : "l"(v));
}
__device__ __forceinline__ u64 fma2(u64 a, u64 b, u64 c) {
    u64 d;
    asm("fma.rn.f32x2 %0, %1, %2, %3;" : "=l"(d) : "l"(a), "l"(b), "l"(c));
    return d;
}
__device__ __forceinline__ u64 mul2(u64 a, u64 b) {
    u64 d;
    asm("mul.rn.f32x2 %0, %1, %2;" : "=l"(d) : "l"(a), "l"(b));
    return d;
}
__device__ __forceinline__ float sqrt_approx(float x) {
    float r;
    asm("sqrt.approx.f32 %0, %1;" : "=f"(r) : "f"(x));
    return r;
}
__device__ __forceinline__ float sin_ap(float x) {
    float r;
    asm("sin.approx.f32 %0, %1;" : "=f"(r) : "f"(x));
    return r;
}
__device__ __forceinline__ float cos_ap(float x) {
    float r;
    asm("cos.approx.f32 %0, %1;" : "=f"(r) : "f"(x));
    return r;
}

// Gram factorization, Re only, f32x2-packed, HW-only range reduction,
// software-pipelined loads (prefetch next source while computing current):
//   Re(vis_ij)(t,f) = sum_s u_i*u_j + v_i*v_j
//   (u_a, v_a) = g_a*(cos ph_a, sin ph_a), ph_a = -2*pi*f*(r_a.s_hat)/C
__global__ __launch_bounds__(NTHREADS, 4) void rime_gram_re_kernel(
    const float* __restrict__ sky,      // [NF, NS]
    const float* __restrict__ beam,     // [2, NT, NF, NS]
    const float* __restrict__ antpos,   // [NANTS, 3]
    const float* __restrict__ src,      // [NT, NS, 3]
    const float* __restrict__ freqs,    // [NF]
    const int*   __restrict__ a2m,      // [NANTS]
    const int*   __restrict__ bls,      // [NBL, 2]
    float*       __restrict__ out)      // [NBL, NT, NF] float32 = Re(vis)
{
    const int tf  = blockIdx.x;
    const int t   = tf >> 5;
    const int f   = tf & (NF - 1);
    const int tid = threadIdx.x;

    const float kc = __ldg(&freqs[f]) * NEG_2PI_OVER_C;

    // Packed per-antenna-pair phase coefficients: lanes = antennas (2q, 2q+1)
    u64 KX[NANTS / 2], KY[NANTS / 2], KZ[NANTS / 2];
    int m[NANTS];
#pragma unroll
    for (int q = 0; q < NANTS / 2; q++) {
        const int a = 2 * q, b = 2 * q + 1;
        KX[q] = pack2(kc * __ldg(&antpos[a * 3 + 0]), kc * __ldg(&antpos[b * 3 + 0]));
        KY[q] = pack2(kc * __ldg(&antpos[a * 3 + 1]), kc * __ldg(&antpos[b * 3 + 1]));
        KZ[q] = pack2(kc * __ldg(&antpos[a * 3 + 2]), kc * __ldg(&antpos[b * 3 + 2]));
    }
#pragma unroll
    for (int a = 0; a < NANTS; a++) m[a] = __ldg(&a2m[a]);

    // Packed accumulators: acc2[p] = (sum u_i*u_j, sum v_i*v_j)
    u64 acc2[NBL];
#pragma unroll
    for (int p = 0; p < NBL; p++) acc2[p] = 0ull;

    const float* __restrict__ beam0 = beam + ((size_t)(0 * NT + t) * NF + f) * NS;
    const float* __restrict__ beam1 = beam + ((size_t)(1 * NT + t) * NF + f) * NS;
    const float* __restrict__ skyf  = sky + (size_t)f * NS;
    const float* __restrict__ srct  = src + (size_t)t * NS * 3;

    // ---- software pipeline: prefetch iteration k+1 while computing k ----
    float dx, dy, dz, sk, b0, b1;                 // current
    {
        const int s = tid;
        dx = __ldg(&srct[s * 3 + 0]);
        dy = __ldg(&srct[s * 3 + 1]);
        dz = __ldg(&srct[s * 3 + 2]);
        sk = __ldg(&skyf[s]);
        b0 = __ldg(&beam0[s]);
        b1 = __ldg(&beam1[s]);
    }

#pragma unroll
    for (int k = 0; k < NITER; k++) {
        float ndx, ndy, ndz, nsk, nb0, nb1;
        if (k + 1 < NITER) {                       // prefetch next source
            const int s = tid + (k + 1) * NTHREADS;
            ndx = __ldg(&srct[s * 3 + 0]);
            ndy = __ldg(&srct[s * 3 + 1]);
            ndz = __ldg(&srct[s * 3 + 2]);
            nsk = __ldg(&skyf[s]);
            nb0 = __ldg(&beam0[s]);
            nb1 = __ldg(&beam1[s]);
        }

        const float rsk = sqrt_approx(sk);
        const float g0 = b0 * rsk;
        const float g1 = b1 * rsk;
        const u64 G0 = pack2(g0, g0), G1 = pack2(g1, g1);
        const u64 DX = pack2(dx, dx), DY = pack2(dy, dy), DZ = pack2(dz, dz);

        u64 U[NANTS];   // U[a] = (g_a*cos, g_a*sin)
#pragma unroll
        for (int q = 0; q < NANTS / 2; q++) {
            const u64 ph2 = fma2(KX[q], DX, fma2(KY[q], DY, mul2(KZ[q], DZ)));
            float pha, phb;
            unpack2(ph2, pha, phb);
#pragma unroll
            for (int h = 0; h < 2; h++) {
                const float ph = h ? phb : pha;
                const int a = 2 * q + h;
                // MUFU HW range reduction only: |ph|<=320 rad -> ~4e-5 rad err
                const float cs = cos_ap(ph);
                const float sn = sin_ap(ph);
                U[a] = mul2(pack2(cs, sn), m[a] ? G1 : G0);
            }
        }

        int p = 0;
#pragma unroll
        for (int i = 0; i < NANTS; i++) {
#pragma unroll
            for (int j = i + 1; j < NANTS; j++) {
                acc2[p] = fma2(U[i], U[j], acc2[p]);   // (uu, vv) accumulate
                p++;
            }
        }

        if (k + 1 < NITER) {
            dx = ndx; dy = ndy; dz = ndz; sk = nsk; b0 = nb0; b1 = nb1;
        }
    }

    // Unpack to Re = uu + vv, then intra-warp butterfly reduction.
    float accr[NBL];
#pragma unroll
    for (int p = 0; p < NBL; p++) {
        float lo, hi;
        unpack2(acc2[p], lo, hi);
        accr[p] = lo + hi;
    }
#pragma unroll
    for (int p = 0; p < NBL; p++) {
#pragma unroll
        for (int off = 16; off > 0; off >>= 1) {
            accr[p] += __shfl_xor_sync(0xffffffffu, accr[p], off);
        }
    }

    __shared__ float red[NWARPS][NBL];
    const int w = tid >> 5, lane = tid & 31;
    if (lane == 0) {
#pragma unroll
        for (int p = 0; p < NBL; p++) red[w][p] = accr[p];
    }
    __syncthreads();

    if (tid < NBL) {
        // bls verified canonical (i<j ascending); remap kept for robustness.
        int bi = __ldg(&bls[2 * tid]);
        int bj = __ldg(&bls[2 * tid + 1]);
        if (bi > bj) { int tmp = bi; bi = bj; bj = tmp; }
        const int pc = bi * (2 * NANTS - bi - 1) / 2 + (bj - bi - 1);
        float r = 0.0f;
#pragma unroll
        for (int ww = 0; ww < NWARPS; ww++) r += red[ww][pc];
        out[(tid * NT + t) * NF + f] = r;   // (b, t, f) C-order, Re(vis)
    }
}

extern "C" void kernel_launch(void* const* d_in, const int* in_sizes, int n_in,
                              void* d_out, int out_size) {
    (void)out_size;
    const float* sky = nullptr;     // 32768
    const float* beam = nullptr;    // 1048576
    const float* antpos = nullptr;  // 24
    const float* src = nullptr;     // 49152
    const float* freqs = nullptr;   // 32
    const int*   a2m = nullptr;     // 8
    const int*   bls = nullptr;     // 56
    for (int k = 0; k < n_in; k++) {
        switch (in_sizes[k]) {
            case 32768:   sky    = (const float*)d_in[k]; break;
            case 1048576: beam   = (const float*)d_in[k]; break;
            case 24:      antpos = (const float*)d_in[k]; break;
            case 49152:   src    = (const float*)d_in[k]; break;
            case 32:      freqs  = (const float*)d_in[k]; break;
            case 8:       a2m    = (const int*)d_in[k];   break;
            case 56:      bls    = (const int*)d_in[k];   break;
            default: break;
        }
    }

    rime_gram_re_kernel<<<NT * NF, NTHREADS>>>(
        sky, beam, antpos, src, freqs, a2m, bls, (float*)d_out);
}

// round 17
// speedup vs baseline: 1.4656x; 1.0156x over previous
#include <cuda_runtime.h>

#define NANTS 8
#define NT 16
#define NF 32
#define NS 1024
#define NBL 28
#define NTHREADS 128
#define NWARPS (NTHREADS / 32)
#define NITER (NS / NTHREADS)   // 8 sources per thread
#define RSTRIDE 129              // padded row stride (words) -> conflict-free

#define NEG_2PI_OVER_C (-2.0958450219516946e-8f)  // -2*pi / 299792458 (exact C)

typedef unsigned long long u64;

__device__ __forceinline__ u64 pack2(float lo, float hi) {
    u64 r;
    asm("mov.b64 %0, {%1, %2};" : "=l"(r) : "f"(lo), "f"(hi));
    return r;
}
__device__ __forceinline__ void unpack2(u64 v, float& lo, float& hi) {
    asm("mov.b64 {%0, %1}, %2;" : "=f"(lo), "=f"(hi) : "l"(v));
}
__device__ __forceinline__ u64 fma2(u64 a, u64 b, u64 c) {
    u64 d;
    asm("fma.rn.f32x2 %0, %1, %2, %3;" : "=l"(d) : "l"(a), "l"(b), "l"(c));
    return d;
}
__device__ __forceinline__ u64 mul2(u64 a, u64 b) {
    u64 d;
    asm("mul.rn.f32x2 %0, %1, %2;" : "=l"(d) : "l"(a), "l"(b));
    return d;
}
__device__ __forceinline__ float sqrt_approx(float x) {
    float r;
    asm("sqrt.approx.f32 %0, %1;" : "=f"(r) : "f"(x));
    return r;
}
__device__ __forceinline__ float sin_ap(float x) {
    float r;
    asm("sin.approx.f32 %0, %1;" : "=f"(r) : "f"(x));
    return r;
}
__device__ __forceinline__ float cos_ap(float x) {
    float r;
    asm("cos.approx.f32 %0, %1;" : "=f"(r) : "f"(x));
    return r;
}

// Gram factorization, Re only, f32x2-packed, HW-only range reduction,
// software-pipelined loads, smem scatter + column-sum reduction tail:
//   Re(vis_ij)(t,f) = sum_s u_i*u_j + v_i*v_j
//   (u_a, v_a) = g_a*(cos ph_a, sin ph_a), ph_a = -2*pi*f*(r_a.s_hat)/C
__global__ __launch_bounds__(NTHREADS, 4) void rime_gram_re_kernel(
    const float* __restrict__ sky,      // [NF, NS]
    const float* __restrict__ beam,     // [2, NT, NF, NS]
    const float* __restrict__ antpos,   // [NANTS, 3]
    const float* __restrict__ src,      // [NT, NS, 3]
    const float* __restrict__ freqs,    // [NF]
    const int*   __restrict__ a2m,      // [NANTS]
    const int*   __restrict__ bls,      // [NBL, 2]
    float*       __restrict__ out)      // [NBL, NT, NF] float32 = Re(vis)
{
    const int tf  = blockIdx.x;
    const int t   = tf >> 5;
    const int f   = tf & (NF - 1);
    const int tid = threadIdx.x;

    const float kc = __ldg(&freqs[f]) * NEG_2PI_OVER_C;

    // Packed per-antenna-pair phase coefficients: lanes = antennas (2q, 2q+1)
    u64 KX[NANTS / 2], KY[NANTS / 2], KZ[NANTS / 2];
    int m[NANTS];
#pragma unroll
    for (int q = 0; q < NANTS / 2; q++) {
        const int a = 2 * q, b = 2 * q + 1;
        KX[q] = pack2(kc * __ldg(&antpos[a * 3 + 0]), kc * __ldg(&antpos[b * 3 + 0]));
        KY[q] = pack2(kc * __ldg(&antpos[a * 3 + 1]), kc * __ldg(&antpos[b * 3 + 1]));
        KZ[q] = pack2(kc * __ldg(&antpos[a * 3 + 2]), kc * __ldg(&antpos[b * 3 + 2]));
    }
#pragma unroll
    for (int a = 0; a < NANTS; a++) m[a] = __ldg(&a2m[a]);

    // Packed accumulators: acc2[p] = (sum u_i*u_j, sum v_i*v_j)
    u64 acc2[NBL];
#pragma unroll
    for (int p = 0; p < NBL; p++) acc2[p] = 0ull;

    const float* __restrict__ beam0 = beam + ((size_t)(0 * NT + t) * NF + f) * NS;
    const float* __restrict__ beam1 = beam + ((size_t)(1 * NT + t) * NF + f) * NS;
    const float* __restrict__ skyf  = sky + (size_t)f * NS;
    const float* __restrict__ srct  = src + (size_t)t * NS * 3;

    // ---- software pipeline: prefetch iteration k+1 while computing k ----
    float dx, dy, dz, sk, b0, b1;
    {
        const int s = tid;
        dx = __ldg(&srct[s * 3 + 0]);
        dy = __ldg(&srct[s * 3 + 1]);
        dz = __ldg(&srct[s * 3 + 2]);
        sk = __ldg(&skyf[s]);
        b0 = __ldg(&beam0[s]);
        b1 = __ldg(&beam1[s]);
    }

#pragma unroll
    for (int k = 0; k < NITER; k++) {
        float ndx, ndy, ndz, nsk, nb0, nb1;
        if (k + 1 < NITER) {
            const int s = tid + (k + 1) * NTHREADS;
            ndx = __ldg(&srct[s * 3 + 0]);
            ndy = __ldg(&srct[s * 3 + 1]);
            ndz = __ldg(&srct[s * 3 + 2]);
            nsk = __ldg(&skyf[s]);
            nb0 = __ldg(&beam0[s]);
            nb1 = __ldg(&beam1[s]);
        }

        const float rsk = sqrt_approx(sk);
        const float g0 = b0 * rsk;
        const float g1 = b1 * rsk;
        const u64 G0 = pack2(g0, g0), G1 = pack2(g1, g1);
        const u64 DX = pack2(dx, dx), DY = pack2(dy, dy), DZ = pack2(dz, dz);

        u64 U[NANTS];   // U[a] = (g_a*cos, g_a*sin)
#pragma unroll
        for (int q = 0; q < NANTS / 2; q++) {
            const u64 ph2 = fma2(KX[q], DX, fma2(KY[q], DY, mul2(KZ[q], DZ)));
            float pha, phb;
            unpack2(ph2, pha, phb);
#pragma unroll
            for (int h = 0; h < 2; h++) {
                const float ph = h ? phb : pha;
                const int a = 2 * q + h;
                const float cs = cos_ap(ph);   // MUFU HW range reduction only
                const float sn = sin_ap(ph);
                U[a] = mul2(pack2(cs, sn), m[a] ? G1 : G0);
            }
        }

        int p = 0;
#pragma unroll
        for (int i = 0; i < NANTS; i++) {
#pragma unroll
            for (int j = i + 1; j < NANTS; j++) {
                acc2[p] = fma2(U[i], U[j], acc2[p]);   // (uu, vv) accumulate
                p++;
            }
        }

        if (k + 1 < NITER) {
            dx = ndx; dy = ndy; dz = ndz; sk = nsk; b0 = nb0; b1 = nb1;
        }
    }

    // ---- reduction: smem scatter + parallel column-sum (no warp butterfly) ----
    __shared__ float red[NBL][RSTRIDE];   // row p: 128 partials (+pad)
    __shared__ float part[NWARPS][NBL];

#pragma unroll
    for (int p = 0; p < NBL; p++) {
        float lo, hi;
        unpack2(acc2[p], lo, hi);
        red[p][tid] = lo + hi;            // lane-stride 1 -> conflict-free
    }
    __syncthreads();

    // Stage A: warp w, lane l (<28) sums red[l][32w .. 32w+31]
    {
        const int w = tid >> 5, lane = tid & 31;
        if (lane < NBL) {
            const float* row = &red[lane][w * 32];
            float s0 = 0.f, s1 = 0.f, s2 = 0.f, s3 = 0.f;
#pragma unroll
            for (int j = 0; j < 32; j += 4) {
                s0 += row[j + 0];
                s1 += row[j + 1];
                s2 += row[j + 2];
                s3 += row[j + 3];
            }
            part[w][lane] = (s0 + s1) + (s2 + s3);
        }
    }
    __syncthreads();

    // Stage B: 28 threads combine the 4 warp partials and write out.
    if (tid < NBL) {
        // bls verified canonical (i<j ascending); remap kept for robustness.
        int bi = __ldg(&bls[2 * tid]);
        int bj = __ldg(&bls[2 * tid + 1]);
        if (bi > bj) { int tmp = bi; bi = bj; bj = tmp; }
        const int pc = bi * (2 * NANTS - bi - 1) / 2 + (bj - bi - 1);
        const float r = (part[0][pc] + part[1][pc]) + (part[2][pc] + part[3][pc]);
        out[(tid * NT + t) * NF + f] = r;   // (b, t, f) C-order, Re(vis)
    }
}

extern "C" void kernel_launch(void* const* d_in, const int* in_sizes, int n_in,
                              void* d_out, int out_size) {
    (void)out_size;
    const float* sky = nullptr;     // 32768
    const float* beam = nullptr;    // 1048576
    const float* antpos = nullptr;  // 24
    const float* src = nullptr;     // 49152
    const float* freqs = nullptr;   // 32
    const int*   a2m = nullptr;     // 8
    const int*   bls = nullptr;     // 56
    for (int k = 0; k < n_in; k++) {
        switch (in_sizes[k]) {
            case 32768:   sky    = (const float*)d_in[k]; break;
            case 1048576: beam   = (const float*)d_in[k]; break;
            case 24:      antpos = (const float*)d_in[k]; break;
            case 49152:   src    = (const float*)d_in[k]; break;
            case 32:      freqs  = (const float*)d_in[k]; break;
            case 8:       a2m    = (const int*)d_in[k];   break;
            case 56:      bls    = (const int*)d_in[k];   break;
            default: break;
        }
    }

    rime_gram_re_kernel<<<NT * NF, NTHREADS>>>(
        sky, beam, antpos, src, freqs, a2m, bls, (float*)d_out);
}